// round 14
// baseline (speedup 1.0000x reference)
#include <cuda_runtime.h>
#include <cuda_fp16.h>
#include <math.h>

#define NN 10000
#define EE 320000
#define GG 64
#define HH 32
#define CAP 80    // edge bucket capacity per node (deg ~ Poisson(32); 10-sigma safe)

// ---- scratch (device globals; no allocation allowed) ----
// triple-buffered so no address is read-then-rewritten-then-read within one launch
__device__ __half2 g_PQ1[NN * HH];
__device__ __half2 g_PQ2[NN * HH];
__device__ __half2 g_PQ3[NN * HH];
__device__ float   g_bufA[NN * HH];
__device__ float   g_bufB[NN * HH];
__device__ float   g_bufC[NN * HH];
__device__ float2  g_ep[NN * CAP];      // bucketed {src*HH bits, attr} per dst node
// single contiguous zero region: [bar 8][cur NN][add GG*HH][max GG*HH][cnt GG]
#define ZTOT (8 + NN + 2 * GG * HH + GG)
__device__ int     g_zero[ZTOT];

__device__ __forceinline__ int*   zbar() { return g_zero; }                       // [0..3] arrive, [4..7] release
__device__ __forceinline__ int*   zcur() { return g_zero + 8; }
__device__ __forceinline__ float* zadd() { return (float*)(g_zero + 8 + NN); }
__device__ __forceinline__ int*   zmax() { return g_zero + 8 + NN + GG * HH; }
__device__ __forceinline__ float* zcnt() { return (float*)(g_zero + 8 + NN + 2 * GG * HH); }

// software grid barrier; all gridDim.x blocks are co-resident by construction
__device__ __forceinline__ void grid_barrier(int idx)
{
    __threadfence();            // order my STGs/atomics to device scope (also invalidates L1D)
    __syncthreads();
    if (threadIdx.x == 0) {
        int* arr = zbar();
        volatile int* rel = (volatile int*)(zbar() + 4);
        if (atomicAdd(&arr[idx], 1) == (int)gridDim.x - 1) {
            __threadfence();
            rel[idx] = 1;
        } else {
            while (rel[idx] == 0) { __nanosleep(64); }
        }
    }
    __syncthreads();
}

// gather core (R8 config): smem edge staging + broadcast LDS, 4-edge unroll, half2 PQ.
__device__ __forceinline__ float gather_row(const __half2* __restrict__ PQ,
                                            const float* __restrict__ seedIn,
                                            int node, int lane,
                                            float2* __restrict__ s_stage)
{
    int n_edges = zcur()[node];
    if (n_edges > CAP) n_edges = CAP;
    int beg = node * CAP;
    int end = beg + n_edges;
    float v0 = seedIn[node * HH + lane];
    float v1 = 0.f, v2 = 0.f, v3 = 0.f;

    for (int base = beg; base < end; base += 32) {
        int n = end - base;
        if (n > 32) n = 32;
        if (lane < n) s_stage[lane] = __ldg(&g_ep[base + lane]);
        __syncwarp();

        int j = 0;
        for (; j + 4 <= n; j += 4) {
            float2 e0 = s_stage[j];
            float2 e1 = s_stage[j + 1];
            float2 e2 = s_stage[j + 2];
            float2 e3 = s_stage[j + 3];
            float2 pq0 = __half22float2(__ldg(&PQ[__float_as_int(e0.x) + lane]));
            float2 pq1 = __half22float2(__ldg(&PQ[__float_as_int(e1.x) + lane]));
            float2 pq2 = __half22float2(__ldg(&PQ[__float_as_int(e2.x) + lane]));
            float2 pq3 = __half22float2(__ldg(&PQ[__float_as_int(e3.x) + lane]));
            v0 += fmaf(e0.y, pq0.x, pq0.y);
            v1 += fmaf(e1.y, pq1.x, pq1.y);
            v2 += fmaf(e2.y, pq2.x, pq2.y);
            v3 += fmaf(e3.y, pq3.x, pq3.y);
        }
        for (; j < n; j++) {
            float2 e0 = s_stage[j];
            float2 pq0 = __half22float2(__ldg(&PQ[__float_as_int(e0.x) + lane]));
            v0 += fmaf(e0.y, pq0.x, pq0.y);
        }
        __syncwarp();
    }
    return (v0 + v1) + (v2 + v3);
}

__global__ void __launch_bounds__(256, 6) fused_kernel(
    const float* __restrict__ x, const int* __restrict__ ei,
    const float* __restrict__ ea, const int* __restrict__ batch,
    const float* __restrict__ nnw1, const float* __restrict__ nnb1,
    const float* __restrict__ root1, const float* __restrict__ bias1,
    const float* __restrict__ nnw2, const float* __restrict__ nnb2,
    const float* __restrict__ root2, const float* __restrict__ bias2,
    const float* __restrict__ nnw3, const float* __restrict__ nnb3,
    const float* __restrict__ root3, const float* __restrict__ bias3,
    const float* __restrict__ lin1w, const float* __restrict__ lin1b,
    const float* __restrict__ lin2w, const float* __restrict__ lin2b,
    float* __restrict__ out)
{
    __shared__ float2 s_wb[33 * HH];     // weight union, reloaded per phase
    __shared__ float  s_r[33 * HH];
    __shared__ float  s_bias[HH];
    __shared__ float2 s_stage[8][32];

    const unsigned F = 0xffffffffu;
    int tid  = threadIdx.x;
    int wid  = tid >> 5;
    int lane = tid & 31;
    int gw   = blockIdx.x * 8 + wid;     // global warp id
    int nw   = gridDim.x * 8;

    // ================= phase 1: layer-1 projection + edge bucketing =================
    for (int i = tid; i < 33 * HH; i += 256) {
        s_wb[i] = make_float2(nnw1[i], nnb1[i]);
        s_r[i]  = root1[i];
    }
    if (tid < HH) s_bias[tid] = bias1[tid];
    __syncthreads();

    for (int row = gw; row < NN; row += nw) {
        const float* xr = x + (size_t)row * 33;
        float ap = 0.f, aq = 0.f, ar = s_bias[lane];
        #pragma unroll
        for (int k = 0; k < 33; k++) {
            float xv = __ldg(xr + k);
            float2 wb = s_wb[k * HH + lane];
            float  rr = s_r[k * HH + lane];
            ap = fmaf(xv, wb.x, ap); aq = fmaf(xv, wb.y, aq); ar = fmaf(xv, rr, ar);
        }
        g_PQ1[row * HH + lane]  = __floats2half2_rn(ap, aq);
        g_bufA[row * HH + lane] = ar;
    }
    {
        int* cur = zcur();
        int stride = gridDim.x * 256 * 8;
        for (int e = (blockIdx.x * 256 + tid) * 8; e < EE; e += stride) {
            #pragma unroll
            for (int h = 0; h < 2; h++) {
                int4   s4 = *(const int4*)(ei + e + h * 4);
                int4   d4 = *(const int4*)(ei + EE + e + h * 4);
                float4 a4 = *(const float4*)(ea + e + h * 4);
                int p0 = atomicAdd(&cur[d4.x], 1);
                int p1 = atomicAdd(&cur[d4.y], 1);
                int p2 = atomicAdd(&cur[d4.z], 1);
                int p3 = atomicAdd(&cur[d4.w], 1);
                if (p0 < CAP) g_ep[d4.x * CAP + p0] = make_float2(__int_as_float(s4.x * HH), a4.x);
                if (p1 < CAP) g_ep[d4.y * CAP + p1] = make_float2(__int_as_float(s4.y * HH), a4.y);
                if (p2 < CAP) g_ep[d4.z * CAP + p2] = make_float2(__int_as_float(s4.z * HH), a4.z);
                if (p3 < CAP) g_ep[d4.w * CAP + p3] = make_float2(__int_as_float(s4.w * HH), a4.w);
            }
        }
    }
    grid_barrier(0);

    // ================= phase 2: gather L1 + proj L2 =================
    for (int i = tid; i < HH * HH; i += 256) {
        s_wb[i] = make_float2(nnw2[i], nnb2[i]);
        s_r[i]  = root2[i];
    }
    if (tid < HH) s_bias[tid] = bias2[tid];
    __syncthreads();

    for (int node = gw; node < NN; node += nw) {
        float h = fmaxf(gather_row(g_PQ1, g_bufA, node, lane, s_stage[wid]), 0.f);
        float ap = 0.f, aq = 0.f, ar = s_bias[lane];
        #pragma unroll
        for (int k = 0; k < HH; k++) {
            float xv = __shfl_sync(F, h, k);
            float2 wb = s_wb[k * HH + lane];
            float  rr = s_r[k * HH + lane];
            ap = fmaf(xv, wb.x, ap); aq = fmaf(xv, wb.y, aq); ar = fmaf(xv, rr, ar);
        }
        g_PQ2[node * HH + lane]  = __floats2half2_rn(ap, aq);
        g_bufB[node * HH + lane] = ar;
    }
    grid_barrier(1);

    // ================= phase 3: gather L2 + proj L3 =================
    for (int i = tid; i < HH * HH; i += 256) {
        s_wb[i] = make_float2(nnw3[i], nnb3[i]);
        s_r[i]  = root3[i];
    }
    if (tid < HH) s_bias[tid] = bias3[tid];
    __syncthreads();

    for (int node = gw; node < NN; node += nw) {
        float h = fmaxf(gather_row(g_PQ2, g_bufB, node, lane, s_stage[wid]), 0.f);
        float ap = 0.f, aq = 0.f, ar = s_bias[lane];
        #pragma unroll
        for (int k = 0; k < HH; k++) {
            float xv = __shfl_sync(F, h, k);
            float2 wb = s_wb[k * HH + lane];
            float  rr = s_r[k * HH + lane];
            ap = fmaf(xv, wb.x, ap); aq = fmaf(xv, wb.y, aq); ar = fmaf(xv, rr, ar);
        }
        g_PQ3[node * HH + lane]  = __floats2half2_rn(ap, aq);
        g_bufC[node * HH + lane] = ar;
    }
    grid_barrier(2);

    // ================= phase 4: gather L3 + pooling =================
    for (int node = gw; node < NN; node += nw) {
        float v = fmaxf(gather_row(g_PQ3, g_bufC, node, lane, s_stage[wid]), 0.f);
        int b = batch[node];
        atomicAdd(&zadd()[b * HH + lane], v);
        atomicMax(&zmax()[b * HH + lane], __float_as_int(v)); // v >= 0: int order ok
        if (lane == 0) atomicAdd(&zcnt()[b], 1.0f);
    }
    grid_barrier(3);

    // ================= phase 5: readout (first 64 warps, one graph each) =================
    if (gw < GG) {
        int gi = gw;
        float addv = zadd()[gi * HH + lane];
        float cnt  = fmaxf(zcnt()[gi], 1.0f);
        float inv  = 1.0f / cnt;
        float mxv  = __int_as_float(zmax()[gi * HH + lane]);

        float acc = lin1b[lane];
        #pragma unroll
        for (int k = 0; k < HH; k++) {
            float a = __shfl_sync(F, addv, k);
            float m = __shfl_sync(F, mxv, k);
            acc = fmaf(a,       lin1w[k * HH + lane],            acc);
            acc = fmaf(a * inv, lin1w[(HH + k) * HH + lane],     acc);
            acc = fmaf(m,       lin1w[(2 * HH + k) * HH + lane], acc);
        }
        float h1 = fmaxf(acc, 0.f);

        float p0 = h1 * lin2w[lane * 2 + 0];
        float p1 = h1 * lin2w[lane * 2 + 1];
        #pragma unroll
        for (int o = 16; o > 0; o >>= 1) {
            p0 += __shfl_xor_sync(F, p0, o);
            p1 += __shfl_xor_sync(F, p1, o);
        }
        if (lane == 0) {
            float l0 = p0 + lin2b[0];
            float l1 = p1 + lin2b[1];
            float mm = fmaxf(l0, l1);
            float lse = mm + logf(expf(l0 - mm) + expf(l1 - mm));
            out[gi * 2 + 0] = l0 - lse;
            out[gi * 2 + 1] = l1 - lse;
        }
    }
}

extern "C" void kernel_launch(void* const* d_in, const int* in_sizes, int n_in,
                              void* d_out, int out_size)
{
    const float* x      = (const float*)d_in[0];
    const int*   ei     = (const int*)d_in[1];
    const float* ea     = (const float*)d_in[2];
    const int*   batch  = (const int*)d_in[3];
    const float* nn_w1  = (const float*)d_in[4];
    const float* nn_b1  = (const float*)d_in[5];
    const float* root1  = (const float*)d_in[6];
    const float* bias1  = (const float*)d_in[7];
    const float* nn_w2  = (const float*)d_in[8];
    const float* nn_b2  = (const float*)d_in[9];
    const float* root2  = (const float*)d_in[10];
    const float* bias2  = (const float*)d_in[11];
    const float* nn_w3  = (const float*)d_in[12];
    const float* nn_b3  = (const float*)d_in[13];
    const float* root3  = (const float*)d_in[14];
    const float* bias3  = (const float*)d_in[15];
    const float* lin1_w = (const float*)d_in[16];
    const float* lin1_b = (const float*)d_in[17];
    const float* lin2_w = (const float*)d_in[18];
    const float* lin2_b = (const float*)d_in[19];
    float* out = (float*)d_out;

    int* dZero;
    cudaGetSymbolAddress((void**)&dZero, g_zero);

    // guaranteed-resident grid: 6 blocks/SM (regs capped 42 via launch_bounds,
    // 14.9 KB static smem, 1536 thr/SM — all within limits)
    int smCount = 148;
    cudaDeviceGetAttribute(&smCount, cudaDevAttrMultiProcessorCount, 0);
    int grid = smCount * 6;

    // one memset zeroes barriers + cur + add + max + cnt
    cudaMemsetAsync(dZero, 0, ZTOT * sizeof(int));

    fused_kernel<<<grid, 256>>>(
        x, ei, ea, batch,
        nn_w1, nn_b1, root1, bias1,
        nn_w2, nn_b2, root2, bias2,
        nn_w3, nn_b3, root3, bias3,
        lin1_w, lin1_b, lin2_w, lin2_b, out);
}